// round 2
// baseline (speedup 1.0000x reference)
#include <cuda_runtime.h>
#include <cstdint>
#include <math.h>

typedef unsigned int u32;
typedef unsigned long long u64;

#define BMAX 4096

// ---------------- device scratch (no allocations allowed) ----------------
__device__ u64 g_q1[BMAX * 196];   // qact1: per (n, y*14+x), bit c = sign of channel c
__device__ u64 g_q2[BMAX * 49];    // qact2: per (n, y*7+x)
__device__ u64 g_w2p[64 * 9];      // conv2 weights packed: (c_out, tap) bits = c_in
__device__ u64 g_f1p[2048 * 49];   // fc1 weights packed: (j, p) bits = channel c (flatten c*49+p)
__device__ u32 g_f2p[10 * 64];     // fc2 weights packed: (k, wi) bits = j = wi*32+l
__device__ int   g_c1q[64];        // conv1 per-channel combo meta
__device__ float g_c1A[64], g_c1B[64];
__device__ float g_c2A[64], g_c2B[64];
__device__ float g_A3[2048], g_B3[2048];

// ---------------- prep: binarize+pack weights, fold bias+bn into (A,B) ----------------
__global__ void prep_kernel(const float* __restrict__ fc1_w, const float* __restrict__ fc2_w,
                            const float* __restrict__ c2w,  const float* __restrict__ c1w,
                            const float* __restrict__ c1b,
                            const float* __restrict__ g1, const float* __restrict__ be1,
                            const float* __restrict__ mu1, const float* __restrict__ va1,
                            const float* __restrict__ c2b,
                            const float* __restrict__ g2, const float* __restrict__ be2,
                            const float* __restrict__ mu2, const float* __restrict__ va2,
                            const float* __restrict__ f1b,
                            const float* __restrict__ g3, const float* __restrict__ be3,
                            const float* __restrict__ mu3, const float* __restrict__ va3)
{
    int i = blockIdx.x * blockDim.x + threadIdx.x;
    if (i < 2048 * 49) {                       // fc1 pack
        int j = i / 49, p = i % 49;
        const float* base = fc1_w + j * 3136 + p;
        u64 w = 0;
        #pragma unroll
        for (int c = 0; c < 64; c++) w |= (u64)(base[c * 49] >= 0.f) << c;
        g_f1p[i] = w;
        return;
    }
    int r = i - 2048 * 49;
    if (r < 640) {                             // fc2 pack (u32 words)
        int k = r / 64, wi = r % 64;
        const float* base = fc2_w + k * 2048 + wi * 32;
        u32 w = 0;
        #pragma unroll
        for (int l = 0; l < 32; l++) w |= (u32)(base[l] >= 0.f) << l;
        g_f2p[r] = w;
        return;
    }
    r -= 640;
    if (r < 576) {                             // conv2 pack
        int c = r / 9, tap = r % 9;
        u64 w = 0;
        #pragma unroll
        for (int ci = 0; ci < 64; ci++)
            w |= (u64)(c2w[(c * 64 + ci) * 9 + tap] >= 0.f) << ci;
        g_w2p[r] = w;
        return;
    }
    r -= 576;
    if (r < 64) {                              // conv1 combo meta + bn1 fold
        int c = r;
        int m = 0;
        #pragma unroll
        for (int k = 0; k < 3; k++) {
            float a = c1w[c * 9 + k * 3], b = c1w[c * 9 + k * 3 + 1], cc = c1w[c * 9 + k * 3 + 2];
            int sa = (a >= 0.f), sb = (b >= 0.f), sc = (cc >= 0.f);
            int q = ((sa ^ sb) ? 2 : 0) | ((sa ^ sc) ? 1 : 0);
            m |= q << (2 * k);
            if (!sa) m |= 1 << (6 + k);
        }
        g_c1q[c] = m;
        float inv = g1[c] * (float)(1.0 / sqrt((double)va1[c] + 1e-5));
        g_c1A[c] = inv;
        g_c1B[c] = inv * c1b[c] + be1[c] - mu1[c] * inv;
        return;
    }
    r -= 64;
    if (r < 64) {                              // bn2 fold
        int c = r;
        float inv = g2[c] * (float)(1.0 / sqrt((double)va2[c] + 1e-5));
        g_c2A[c] = inv;
        g_c2B[c] = inv * c2b[c] + be2[c] - mu2[c] * inv;
        return;
    }
    r -= 64;
    if (r < 2048) {                            // bn3 fold
        int j = r;
        float inv = g3[j] * (float)(1.0 / sqrt((double)va3[j] + 1e-5));
        g_A3[j] = inv;
        g_B3[j] = inv * f1b[j] + be3[j] - mu3[j] * inv;
    }
}

// ---------------- K1: conv1 + bias + maxpool + bn1 + sign -> packed bits ----------------
// Combo planes C0..C3 = {a+b+c, a+b-c, a-b+c, a-b-c} per image row/col pair,
// stored as float2 (the two columns of a pooling pair). Lane = channel; the
// per-channel plane choice q becomes an smem address (<=4 distinct words/warp).
__global__ __launch_bounds__(256) void conv1_kernel(const float* __restrict__ x)
{
    __shared__ float  xs[784];
    __shared__ float2 CF[4 * 30 * 14];   // [plane][imgrow+1 (0..29)][pooled col]
    int n = blockIdx.x;
    int t = threadIdx.x;
    const float* xg = x + n * 784;
    for (int i = t; i < 784; i += 256) xs[i] = xg[i];
    __syncthreads();
    // zero pad rows (storage rows 0 and 29)
    for (int i = t; i < 112; i += 256) {
        int pl = i / 28; int rr = (i / 14) & 1; int px = i % 14;
        CF[pl * 420 + (rr ? 29 : 0) * 14 + px] = make_float2(0.f, 0.f);
    }
    // build combos for image rows 0..27 (storage rows 1..28)
    for (int i = t; i < 392; i += 256) {
        int ry = i / 14, px = i % 14;
        int x0 = 2 * px;
        float am = (x0 > 0)      ? xs[ry * 28 + x0 - 1] : 0.f;
        float b0 = xs[ry * 28 + x0];
        float b1 = xs[ry * 28 + x0 + 1];
        float ap = (x0 + 2 < 28) ? xs[ry * 28 + x0 + 2] : 0.f;
        int row = ry + 1;
        float s0a = am + b0, d0a = am - b0;
        float s1a = b0 + b1, d1a = b0 - b1;
        CF[0 * 420 + row * 14 + px] = make_float2(s0a + b1, s1a + ap);
        CF[1 * 420 + row * 14 + px] = make_float2(s0a - b1, s1a - ap);
        CF[2 * 420 + row * 14 + px] = make_float2(d0a + b1, d1a + ap);
        CF[3 * 420 + row * 14 + px] = make_float2(d0a - b1, d1a - ap);
    }
    __syncthreads();

    int w = t >> 5, lane = t & 31;
    int half = w & 1, wg = w >> 1;
    int c = half * 32 + lane;
    int m = g_c1q[c];
    float A = g_c1A[c], Bc = g_c1B[c];
    int o0 = (m & 3) * 420;
    int o1 = ((m >> 2) & 3) * 420 + 14;
    int o2 = ((m >> 4) & 3) * 420 + 28;
    float s0 = (m & 0x40)  ? -1.f : 1.f;
    float s1 = (m & 0x80)  ? -1.f : 1.f;
    float s2 = (m & 0x100) ? -1.f : 1.f;

    for (int p = wg; p < 196; p += 4) {
        int py = p / 14, px = p % 14;
        int base = (2 * py) * 14 + px;       // conv row y0 -> storage rows y0..y0+2
        float2 a0 = CF[o0 + base],      b0v = CF[o1 + base],      c0 = CF[o2 + base];
        float2 a1 = CF[o0 + base + 14], b1v = CF[o1 + base + 14], c1 = CF[o2 + base + 14];
        float v0x = fmaf(s0, a0.x, fmaf(s1, b0v.x, s2 * c0.x));
        float v0y = fmaf(s0, a0.y, fmaf(s1, b0v.y, s2 * c0.y));
        float v1x = fmaf(s0, a1.x, fmaf(s1, b1v.x, s2 * c1.x));
        float v1y = fmaf(s0, a1.y, fmaf(s1, b1v.y, s2 * c1.y));
        float mx = fmaxf(fmaxf(v0x, v0y), fmaxf(v1x, v1y));
        u32 mask = __ballot_sync(0xffffffffu, fmaf(A, mx, Bc) >= 0.f);
        if (lane == 0) ((u32*)&g_q1[n * 196 + p])[half] = mask;
    }
}

// ---------------- K2: binary conv2 + maxpool + bn2 + sign -> packed bits ----------------
__global__ __launch_bounds__(256) void conv2_kernel()
{
    __shared__ u64 sa[196];
    __shared__ u64 sw[576];
    int n = blockIdx.x, t = threadIdx.x;
    for (int i = t; i < 196; i += 256) sa[i] = g_q1[n * 196 + i];
    for (int i = t; i < 576; i += 256) sw[i] = g_w2p[i];
    __syncthreads();

    int w = t >> 5, lane = t & 31;
    int half = w & 1, wg = w >> 1;
    int c = half * 32 + lane;
    u64 wr[9];
    #pragma unroll
    for (int k = 0; k < 9; k++) wr[k] = sw[c * 9 + k];
    float A = g_c2A[c], Bc = g_c2B[c];

    for (int p = wg; p < 49; p += 4) {
        int py = p / 7, px = p % 7;
        int y0 = 2 * py, x0 = 2 * px;
        int mx = -100000;
        #pragma unroll
        for (int yy = 0; yy < 2; yy++) {
            #pragma unroll
            for (int xx = 0; xx < 2; xx++) {
                int y = y0 + yy, xc = x0 + xx;
                int pc = 0, nv = 0;
                #pragma unroll
                for (int dy = -1; dy <= 1; dy++) {
                    int iy = y + dy;
                    if (iy < 0 || iy >= 14) continue;
                    #pragma unroll
                    for (int dx = -1; dx <= 1; dx++) {
                        int ix = xc + dx;
                        if (ix < 0 || ix >= 14) continue;
                        pc += __popcll(sa[iy * 14 + ix] ^ wr[(dy + 1) * 3 + (dx + 1)]);
                        nv++;
                    }
                }
                int s = nv * 64 - 2 * pc;    // exact +/-1 dot with zero padding
                mx = max(mx, s);
            }
        }
        u32 mask = __ballot_sync(0xffffffffu, fmaf(A, (float)mx, Bc) >= 0.f);
        if (lane == 0) ((u32*)&g_q2[n * 49 + p])[half] = mask;
    }
}

// ---------------- K3: fc1 (popcount GEMM, 16-sample block) + bn3 + sign + fc2 ----------------
__global__ __launch_bounds__(256) void fc_kernel(const float* __restrict__ fc2_b,
                                                 const float* __restrict__ scale,
                                                 float* __restrict__ out)
{
    __shared__ u64 wt[49 * 65];      // fc1 weight tile, transposed [p][j], pitch 65 vs bank conflicts
    __shared__ u64 a2[16 * 49];      // 16 samples of qact2
    __shared__ u32 q3[16 * 64];      // packed qact3 bits
    __shared__ u32 f2[640];          // fc2 packed weights
    int t = threadIdx.x;
    int n0 = blockIdx.x * 16;
    for (int i = t; i < 784; i += 256) a2[i] = g_q2[n0 * 49 + i];
    for (int i = t; i < 640; i += 256) f2[i] = g_f2p[i];

    int jl = t & 63, grp = t >> 6;       // thread: one j-column x 4 samples
    int half32 = (t >> 5) & 1;
    int lane = t & 31;
    int nb = grp * 4 * 49;

    for (int tt = 0; tt < 32; tt++) {
        __syncthreads();
        for (int f = t; f < 3136; f += 256) {         // coalesced load, transposed store
            int jj = f / 49, p = f % 49;
            wt[p * 65 + jj] = g_f1p[tt * 64 * 49 + f];
        }
        __syncthreads();
        int acc0 = 0, acc1 = 0, acc2 = 0, acc3 = 0;
        #pragma unroll 7
        for (int p = 0; p < 49; p++) {
            u64 wv = wt[p * 65 + jl];
            acc0 += __popcll(wv ^ a2[nb + p]);
            acc1 += __popcll(wv ^ a2[nb + 49 + p]);
            acc2 += __popcll(wv ^ a2[nb + 98 + p]);
            acc3 += __popcll(wv ^ a2[nb + 147 + p]);
        }
        int j = tt * 64 + jl;
        float A = g_A3[j], Bc = g_B3[j];
        int wi = tt * 2 + half32;
        u32 m0 = __ballot_sync(0xffffffffu, fmaf(A, (float)(3136 - 2 * acc0), Bc) >= 0.f);
        u32 m1 = __ballot_sync(0xffffffffu, fmaf(A, (float)(3136 - 2 * acc1), Bc) >= 0.f);
        u32 m2 = __ballot_sync(0xffffffffu, fmaf(A, (float)(3136 - 2 * acc2), Bc) >= 0.f);
        u32 m3 = __ballot_sync(0xffffffffu, fmaf(A, (float)(3136 - 2 * acc3), Bc) >= 0.f);
        if (lane == 0) {
            q3[(grp * 4 + 0) * 64 + wi] = m0;
            q3[(grp * 4 + 1) * 64 + wi] = m1;
            q3[(grp * 4 + 2) * 64 + wi] = m2;
            q3[(grp * 4 + 3) * 64 + wi] = m3;
        }
    }
    __syncthreads();
    if (t < 160) {                                    // fc2 + scale
        int nl = t / 10, k = t % 10;
        int pc = 0;
        #pragma unroll 8
        for (int wi = 0; wi < 64; wi++) pc += __popc(q3[nl * 64 + wi] ^ f2[k * 64 + wi]);
        float v = ((float)(2048 - 2 * pc) + fc2_b[k]) * scale[0];
        out[(n0 + nl) * 10 + k] = v;
    }
}

// ---------------- launch ----------------
extern "C" void kernel_launch(void* const* d_in, const int* in_sizes, int n_in,
                              void* d_out, int out_size)
{
    const float* x   = (const float*)d_in[0];
    const float* c1w = (const float*)d_in[1];
    const float* c1b = (const float*)d_in[2];
    const float* c2w = (const float*)d_in[3];
    const float* c2b = (const float*)d_in[4];
    const float* f1w = (const float*)d_in[5];
    const float* f1b = (const float*)d_in[6];
    const float* f2w = (const float*)d_in[7];
    const float* f2b = (const float*)d_in[8];
    const float* g1  = (const float*)d_in[9];
    const float* be1 = (const float*)d_in[10];
    const float* mu1 = (const float*)d_in[11];
    const float* va1 = (const float*)d_in[12];
    const float* g2  = (const float*)d_in[13];
    const float* be2 = (const float*)d_in[14];
    const float* mu2 = (const float*)d_in[15];
    const float* va2 = (const float*)d_in[16];
    const float* g3  = (const float*)d_in[17];
    const float* be3 = (const float*)d_in[18];
    const float* mu3 = (const float*)d_in[19];
    const float* va3 = (const float*)d_in[20];
    const float* scl = (const float*)d_in[21];

    int B = in_sizes[0] / 784;   // 4096

    int prep_items = 2048 * 49 + 640 + 576 + 64 + 64 + 2048;
    prep_kernel<<<(prep_items + 255) / 256, 256>>>(f1w, f2w, c2w, c1w, c1b,
                                                   g1, be1, mu1, va1,
                                                   c2b, g2, be2, mu2, va2,
                                                   f1b, g3, be3, mu3, va3);
    conv1_kernel<<<B, 256>>>(x);
    conv2_kernel<<<B, 256>>>();
    fc_kernel<<<B / 16, 256>>>(f2b, scl, (float*)d_out);
}

// round 3
// speedup vs baseline: 1.1060x; 1.1060x over previous
#include <cuda_runtime.h>
#include <cstdint>
#include <math.h>

typedef unsigned int u32;
typedef unsigned long long u64;

#define BMAX 4096

// ---------------- device scratch (no allocations allowed) ----------------
__device__ u64 g_q1[BMAX * 196];   // qact1: per (n, y*14+x), bit c = sign of channel c
__device__ u64 g_q2[BMAX * 49];    // qact2: per (n, y*7+x)
__device__ u32 g_q3[BMAX * 64];    // qact3: per n, 2048 bits packed as 64 u32
__device__ u64 g_w2p[64 * 9];      // conv2 weights packed: (c_out, tap) bits = c_in
__device__ u64 g_f1p[32 * 49 * 64];// fc1 weights packed: [tt][p][jl], bits = channel c
__device__ u32 g_f2p[10 * 64];     // fc2 weights packed: (k, wi) bits = j = wi*32+l
__device__ int   g_c1q[64];        // conv1 per-channel combo meta
__device__ float g_c1A[64], g_c1B[64];
__device__ float g_c2A[64], g_c2B[64];
__device__ float g_A3[2048], g_B3[2048];

// ---------------- prep: binarize+pack weights, fold bias+bn into (A,B) ----------------
__global__ void prep_kernel(const float* __restrict__ fc1_w, const float* __restrict__ fc2_w,
                            const float* __restrict__ c2w,  const float* __restrict__ c1w,
                            const float* __restrict__ c1b,
                            const float* __restrict__ g1, const float* __restrict__ be1,
                            const float* __restrict__ mu1, const float* __restrict__ va1,
                            const float* __restrict__ c2b,
                            const float* __restrict__ g2, const float* __restrict__ be2,
                            const float* __restrict__ mu2, const float* __restrict__ va2,
                            const float* __restrict__ f1b,
                            const float* __restrict__ g3, const float* __restrict__ be3,
                            const float* __restrict__ mu3, const float* __restrict__ va3)
{
    int i = blockIdx.x * blockDim.x + threadIdx.x;
    if (i < 2048 * 49) {                       // fc1 pack -> [tt][p][jl] layout
        int j = i / 49, p = i % 49;
        const float* base = fc1_w + j * 3136 + p;
        u64 w = 0;
        #pragma unroll
        for (int c = 0; c < 64; c++) w |= (u64)(base[c * 49] >= 0.f) << c;
        g_f1p[((j >> 6) * 49 + p) * 64 + (j & 63)] = w;
        return;
    }
    int r = i - 2048 * 49;
    if (r < 640) {                             // fc2 pack (u32 words)
        int k = r / 64, wi = r % 64;
        const float* base = fc2_w + k * 2048 + wi * 32;
        u32 w = 0;
        #pragma unroll
        for (int l = 0; l < 32; l++) w |= (u32)(base[l] >= 0.f) << l;
        g_f2p[r] = w;
        return;
    }
    r -= 640;
    if (r < 576) {                             // conv2 pack
        int c = r / 9, tap = r % 9;
        u64 w = 0;
        #pragma unroll
        for (int ci = 0; ci < 64; ci++)
            w |= (u64)(c2w[(c * 64 + ci) * 9 + tap] >= 0.f) << ci;
        g_w2p[r] = w;
        return;
    }
    r -= 576;
    if (r < 64) {                              // conv1 combo meta + bn1 fold
        int c = r;
        int m = 0;
        #pragma unroll
        for (int k = 0; k < 3; k++) {
            float a = c1w[c * 9 + k * 3], b = c1w[c * 9 + k * 3 + 1], cc = c1w[c * 9 + k * 3 + 2];
            int sa = (a >= 0.f), sb = (b >= 0.f), sc = (cc >= 0.f);
            int q = ((sa ^ sb) ? 2 : 0) | ((sa ^ sc) ? 1 : 0);
            m |= q << (2 * k);
            if (!sa) m |= 1 << (6 + k);
        }
        g_c1q[c] = m;
        float inv = g1[c] * (float)(1.0 / sqrt((double)va1[c] + 1e-5));
        g_c1A[c] = inv;
        g_c1B[c] = inv * c1b[c] + be1[c] - mu1[c] * inv;
        return;
    }
    r -= 64;
    if (r < 64) {                              // bn2 fold
        int c = r;
        float inv = g2[c] * (float)(1.0 / sqrt((double)va2[c] + 1e-5));
        g_c2A[c] = inv;
        g_c2B[c] = inv * c2b[c] + be2[c] - mu2[c] * inv;
        return;
    }
    r -= 64;
    if (r < 2048) {                            // bn3 fold
        int j = r;
        float inv = g3[j] * (float)(1.0 / sqrt((double)va3[j] + 1e-5));
        g_A3[j] = inv;
        g_B3[j] = inv * f1b[j] + be3[j] - mu3[j] * inv;
    }
}

// ---------------- K1: conv1 + bias + maxpool + bn1 + sign -> packed bits ----------------
__global__ __launch_bounds__(256) void conv1_kernel(const float* __restrict__ x)
{
    __shared__ float  xs[784];
    __shared__ float2 CF[4 * 30 * 14];   // [plane][imgrow+1 (0..29)][pooled col]
    int n = blockIdx.x;
    int t = threadIdx.x;
    const float* xg = x + n * 784;
    for (int i = t; i < 784; i += 256) xs[i] = xg[i];
    __syncthreads();
    for (int i = t; i < 112; i += 256) {
        int pl = i / 28; int rr = (i / 14) & 1; int px = i % 14;
        CF[pl * 420 + (rr ? 29 : 0) * 14 + px] = make_float2(0.f, 0.f);
    }
    for (int i = t; i < 392; i += 256) {
        int ry = i / 14, px = i % 14;
        int x0 = 2 * px;
        float am = (x0 > 0)      ? xs[ry * 28 + x0 - 1] : 0.f;
        float b0 = xs[ry * 28 + x0];
        float b1 = xs[ry * 28 + x0 + 1];
        float ap = (x0 + 2 < 28) ? xs[ry * 28 + x0 + 2] : 0.f;
        int row = ry + 1;
        float s0a = am + b0, d0a = am - b0;
        float s1a = b0 + b1, d1a = b0 - b1;
        CF[0 * 420 + row * 14 + px] = make_float2(s0a + b1, s1a + ap);
        CF[1 * 420 + row * 14 + px] = make_float2(s0a - b1, s1a - ap);
        CF[2 * 420 + row * 14 + px] = make_float2(d0a + b1, d1a + ap);
        CF[3 * 420 + row * 14 + px] = make_float2(d0a - b1, d1a - ap);
    }
    __syncthreads();

    int w = t >> 5, lane = t & 31;
    int half = w & 1, wg = w >> 1;
    int c = half * 32 + lane;
    int m = g_c1q[c];
    float A = g_c1A[c], Bc = g_c1B[c];
    int o0 = (m & 3) * 420;
    int o1 = ((m >> 2) & 3) * 420 + 14;
    int o2 = ((m >> 4) & 3) * 420 + 28;
    float s0 = (m & 0x40)  ? -1.f : 1.f;
    float s1 = (m & 0x80)  ? -1.f : 1.f;
    float s2 = (m & 0x100) ? -1.f : 1.f;

    for (int p = wg; p < 196; p += 4) {
        int py = p / 14, px = p % 14;
        int base = (2 * py) * 14 + px;
        float2 a0 = CF[o0 + base],      b0v = CF[o1 + base],      c0 = CF[o2 + base];
        float2 a1 = CF[o0 + base + 14], b1v = CF[o1 + base + 14], c1 = CF[o2 + base + 14];
        float v0x = fmaf(s0, a0.x, fmaf(s1, b0v.x, s2 * c0.x));
        float v0y = fmaf(s0, a0.y, fmaf(s1, b0v.y, s2 * c0.y));
        float v1x = fmaf(s0, a1.x, fmaf(s1, b1v.x, s2 * c1.x));
        float v1y = fmaf(s0, a1.y, fmaf(s1, b1v.y, s2 * c1.y));
        float mx = fmaxf(fmaxf(v0x, v0y), fmaxf(v1x, v1y));
        u32 mask = __ballot_sync(0xffffffffu, fmaf(A, mx, Bc) >= 0.f);
        if (lane == 0) ((u32*)&g_q1[n * 196 + p])[half] = mask;
    }
}

// ---------------- K2: binary conv2 + maxpool + bn2 + sign -> packed bits ----------------
// Padded 16x16 tile (zero pad words); interior pooled pixels branch-free,
// edge pixels use exact correction corr = sum over pad taps of (64 - 2*popc(w)).
__global__ __launch_bounds__(256) void conv2_kernel()
{
    __shared__ u64 sa[256];          // padded [y+1][x+1], 16x16
    __shared__ u64 sw[576];
    int n = blockIdx.x, t = threadIdx.x;
    {
        int y = t >> 4, xcol = t & 15;
        u64 v = 0;
        if (y >= 1 && y <= 14 && xcol >= 1 && xcol <= 14)
            v = g_q1[n * 196 + (y - 1) * 14 + (xcol - 1)];
        sa[t] = v;
    }
    for (int i = t; i < 576; i += 256) sw[i] = g_w2p[i];
    __syncthreads();

    int w = t >> 5, lane = t & 31;
    int half = w & 1, wg = w >> 1;
    int c = half * 32 + lane;
    u64 wr[9];
    #pragma unroll
    for (int k = 0; k < 9; k++) wr[k] = sw[c * 9 + k];
    int e0 = 64 - 2 * __popcll(wr[0]);
    int e1 = 64 - 2 * __popcll(wr[1]);
    int e2 = 64 - 2 * __popcll(wr[2]);
    int e3 = 64 - 2 * __popcll(wr[3]);
    int e5 = 64 - 2 * __popcll(wr[5]);
    int e6 = 64 - 2 * __popcll(wr[6]);
    int e7 = 64 - 2 * __popcll(wr[7]);
    int e8 = 64 - 2 * __popcll(wr[8]);
    int ET = e0 + e1 + e2, EB = e6 + e7 + e8;
    int EL = e0 + e3 + e6, ER = e2 + e5 + e8;
    float A = g_c2A[c], Bc = g_c2B[c];

    for (int p = wg; p < 49; p += 4) {
        int py = p / 7, px = p % 7;
        int y0 = 2 * py, x0 = 2 * px;
        int mx;
        if (py >= 1 && py <= 5 && px >= 1 && px <= 5) {   // warp-uniform branch
            mx = -100000;
            #pragma unroll
            for (int yy = 0; yy < 2; yy++) {
                #pragma unroll
                for (int xx = 0; xx < 2; xx++) {
                    const u64* b = sa + (y0 + yy) * 16 + (x0 + xx);
                    int pc = 0;
                    #pragma unroll
                    for (int r = 0; r < 3; r++) {
                        pc += __popcll(b[r * 16 + 0] ^ wr[r * 3 + 0]);
                        pc += __popcll(b[r * 16 + 1] ^ wr[r * 3 + 1]);
                        pc += __popcll(b[r * 16 + 2] ^ wr[r * 3 + 2]);
                    }
                    mx = max(mx, 576 - 2 * pc);
                }
            }
        } else {
            mx = -100000;
            #pragma unroll
            for (int yy = 0; yy < 2; yy++) {
                #pragma unroll
                for (int xx = 0; xx < 2; xx++) {
                    int y = y0 + yy, xc = x0 + xx;
                    const u64* b = sa + y * 16 + xc;
                    int pc = 0;
                    #pragma unroll
                    for (int r = 0; r < 3; r++) {
                        pc += __popcll(b[r * 16 + 0] ^ wr[r * 3 + 0]);
                        pc += __popcll(b[r * 16 + 1] ^ wr[r * 3 + 1]);
                        pc += __popcll(b[r * 16 + 2] ^ wr[r * 3 + 2]);
                    }
                    int corr = 0;
                    if (y == 0)  corr += ET;
                    if (y == 13) corr += EB;
                    if (xc == 0)  corr += EL;
                    if (xc == 13) corr += ER;
                    if (y == 0 && xc == 0)   corr -= e0;
                    if (y == 0 && xc == 13)  corr -= e2;
                    if (y == 13 && xc == 0)  corr -= e6;
                    if (y == 13 && xc == 13) corr -= e8;
                    mx = max(mx, 576 - 2 * pc - corr);
                }
            }
        }
        u32 mask = __ballot_sync(0xffffffffu, fmaf(A, (float)mx, Bc) >= 0.f);
        if (lane == 0) ((u32*)&g_q2[n * 49 + p])[half] = mask;
    }
}

// ---------------- K3a: fc1 popcount GEMM, one (16-sample, 64-j tile) per block ----------------
__global__ __launch_bounds__(256) void fc1_kernel()
{
    __shared__ u64 wt[49 * 64];      // [p][jl]
    __shared__ u64 a2[16 * 49];
    int bx = blockIdx.x;
    int tt = bx & 31;
    int n0 = (bx >> 5) << 4;
    int t = threadIdx.x;
    const u64* wsrc = g_f1p + tt * 3136;
    for (int i = t; i < 3136; i += 256) wt[i] = wsrc[i];
    for (int i = t; i < 784; i += 256) a2[i] = g_q2[n0 * 49 + i];
    __syncthreads();

    int jl = t & 63, grp = t >> 6;
    int lane = t & 31, half32 = (t >> 5) & 1;
    const u64* ab = a2 + grp * 4 * 49;

    int acc0 = 0, acc1 = 0, acc2 = 0, acc3 = 0;
    #pragma unroll 7
    for (int p = 0; p < 49; p++) {
        u64 wv = wt[p * 64 + jl];
        acc0 += __popcll(wv ^ ab[p]);
        acc1 += __popcll(wv ^ ab[49 + p]);
        acc2 += __popcll(wv ^ ab[98 + p]);
        acc3 += __popcll(wv ^ ab[147 + p]);
    }
    int j = tt * 64 + jl;
    float A = g_A3[j], Bc = g_B3[j];
    u32 m0 = __ballot_sync(0xffffffffu, fmaf(A, (float)(3136 - 2 * acc0), Bc) >= 0.f);
    u32 m1 = __ballot_sync(0xffffffffu, fmaf(A, (float)(3136 - 2 * acc1), Bc) >= 0.f);
    u32 m2 = __ballot_sync(0xffffffffu, fmaf(A, (float)(3136 - 2 * acc2), Bc) >= 0.f);
    u32 m3 = __ballot_sync(0xffffffffu, fmaf(A, (float)(3136 - 2 * acc3), Bc) >= 0.f);
    if (lane == 0) {
        int wi = tt * 2 + half32;
        g_q3[(n0 + grp * 4 + 0) * 64 + wi] = m0;
        g_q3[(n0 + grp * 4 + 1) * 64 + wi] = m1;
        g_q3[(n0 + grp * 4 + 2) * 64 + wi] = m2;
        g_q3[(n0 + grp * 4 + 3) * 64 + wi] = m3;
    }
}

// ---------------- K3b: fc2 + scale ----------------
__global__ __launch_bounds__(256) void fc2_kernel(const float* __restrict__ fc2_b,
                                                  const float* __restrict__ scale,
                                                  float* __restrict__ out)
{
    __shared__ u32 q3[16 * 64];
    __shared__ u32 f2[640];
    int n0 = blockIdx.x * 16;
    int t = threadIdx.x;
    for (int i = t; i < 1024; i += 256) q3[i] = g_q3[n0 * 64 + i];
    for (int i = t; i < 640; i += 256) f2[i] = g_f2p[i];
    __syncthreads();
    if (t < 160) {
        int nl = t / 10, k = t % 10;
        int pc = 0;
        #pragma unroll 8
        for (int wi = 0; wi < 64; wi++) pc += __popc(q3[nl * 64 + wi] ^ f2[k * 64 + wi]);
        out[(n0 + nl) * 10 + k] = ((float)(2048 - 2 * pc) + fc2_b[k]) * scale[0];
    }
}

// ---------------- launch ----------------
extern "C" void kernel_launch(void* const* d_in, const int* in_sizes, int n_in,
                              void* d_out, int out_size)
{
    const float* x   = (const float*)d_in[0];
    const float* c1w = (const float*)d_in[1];
    const float* c1b = (const float*)d_in[2];
    const float* c2w = (const float*)d_in[3];
    const float* c2b = (const float*)d_in[4];
    const float* f1w = (const float*)d_in[5];
    const float* f1b = (const float*)d_in[6];
    const float* f2w = (const float*)d_in[7];
    const float* f2b = (const float*)d_in[8];
    const float* g1  = (const float*)d_in[9];
    const float* be1 = (const float*)d_in[10];
    const float* mu1 = (const float*)d_in[11];
    const float* va1 = (const float*)d_in[12];
    const float* g2  = (const float*)d_in[13];
    const float* be2 = (const float*)d_in[14];
    const float* mu2 = (const float*)d_in[15];
    const float* va2 = (const float*)d_in[16];
    const float* g3  = (const float*)d_in[17];
    const float* be3 = (const float*)d_in[18];
    const float* mu3 = (const float*)d_in[19];
    const float* va3 = (const float*)d_in[20];
    const float* scl = (const float*)d_in[21];

    int B = in_sizes[0] / 784;   // 4096

    int prep_items = 2048 * 49 + 640 + 576 + 64 + 64 + 2048;
    prep_kernel<<<(prep_items + 255) / 256, 256>>>(f1w, f2w, c2w, c1w, c1b,
                                                   g1, be1, mu1, va1,
                                                   c2b, g2, be2, mu2, va2,
                                                   f1b, g3, be3, mu3, va3);
    conv1_kernel<<<B, 256>>>(x);
    conv2_kernel<<<B, 256>>>();
    fc1_kernel<<<(B / 16) * 32, 256>>>();
    fc2_kernel<<<B / 16, 256>>>(f2b, scl, (float*)d_out);
}